// round 1
// baseline (speedup 1.0000x reference)
#include <cuda_runtime.h>
#include <cfloat>
#include <cstddef>

#define B_  2
#define T_  16
#define NP  1024
#define KNN 16
#define TOUT 14
#define C0 6
#define C1 64
#define C2 128
#define C3 256
#define EPSV 1e-5f

#define P1 (B_*T_*NP*KNN)   /* 524288 rows into MLP */
#define PM (B_*T_*NP)       /* 32768 rows after max-k */
#define PT (B_*TOUT*NP)     /* 28672 output rows */

#define BM 128
#define BN 128
#define BK 32
#define PAD 4

// ---------------- scratch (static device globals; no allocations) ----------------
__device__ float g_feats[(size_t)P1*C0];     // 12.6 MB
__device__ float g_h0[(size_t)P1*C1];        // 134 MB (raw, pre-BN)
__device__ float g_h1[(size_t)P1*C2];        // 268 MB (raw, pre-BN)
__device__ float g_xm[(size_t)PM*C3];        // 33.5 MB (raw max-pooled layer2)
__device__ float g_y[(size_t)PT*C3];         // 29 MB (raw temporal conv)
__device__ float g_pA[(P1/128)*C3];          // per-block partial sums  (max 4096*256)
__device__ float g_pB[(P1/128)*C3];          // per-block partial sumsq
__device__ float g_wtT[3*C3*C3];             // wt transposed to [dt][o][c]
__device__ float g_scale[4*256];             // folded BN scale per stage
__device__ float g_shift[4*256];             // folded BN shift per stage

// ---------------- stage 1: KNN trajectory + feature extraction ----------------
__global__ __launch_bounds__(128) void knn_kernel(const float* __restrict__ pts)
{
    __shared__ float spts[NP*3];
    __shared__ float d2s[NP];
    __shared__ float cur[3];
    __shared__ float anchor[3];
    __shared__ int   sel[KNN];
    __shared__ float wv[4];
    __shared__ int   wj[4];

    int b = blockIdx.x / NP;
    int i = blockIdx.x % NP;
    int tid = threadIdx.x;
    int lane = tid & 31, wid = tid >> 5;

    if (tid < 3) cur[tid] = pts[((size_t)(b*T_ + 0)*NP + i)*3 + tid];

    for (int t = 0; t < T_; t++) {
        const float* pt = pts + (size_t)(b*T_ + t)*NP*3;
        const float* pv = pts + (size_t)(b*T_ + (t == 0 ? 0 : t-1))*NP*3;
        for (int e = tid; e < NP*3; e += 128) spts[e] = pt[e];
        __syncthreads();
        float cx = cur[0], cy = cur[1], cz = cur[2];
        for (int j = tid; j < NP; j += 128) {
            float dx = cx - spts[j*3+0];
            float dy = cy - spts[j*3+1];
            float dz = cz - spts[j*3+2];
            d2s[j] = dx*dx + dy*dy + dz*dz;
        }
        __syncthreads();
        for (int k = 0; k < KNN; k++) {
            float bv = FLT_MAX; int bj = NP;
            for (int j = tid; j < NP; j += 128) {
                float v = d2s[j];
                if (v < bv) { bv = v; bj = j; }
            }
            #pragma unroll
            for (int off = 16; off; off >>= 1) {
                float ov = __shfl_down_sync(0xffffffffu, bv, off);
                int   oj = __shfl_down_sync(0xffffffffu, bj, off);
                if (ov < bv || (ov == bv && oj < bj)) { bv = ov; bj = oj; }
            }
            if (lane == 0) { wv[wid] = bv; wj[wid] = bj; }
            __syncthreads();
            if (tid == 0) {
                float mv = wv[0]; int mj = wj[0];
                for (int w = 1; w < 4; w++)
                    if (wv[w] < mv || (wv[w] == mv && wj[w] < mj)) { mv = wv[w]; mj = wj[w]; }
                sel[k] = mj;
                d2s[mj] = FLT_MAX;
                if (k == 0 && t == 0) {
                    anchor[0] = spts[mj*3+0];
                    anchor[1] = spts[mj*3+1];
                    anchor[2] = spts[mj*3+2];
                }
            }
            __syncthreads();
        }
        // write features: [b][t][n][k][6]: c0..2 = pf (prev pts gathered), c3..5 = pp - anchor
        size_t base = ((size_t)((b*T_ + t)*NP) + i) * KNN;
        if (tid < KNN*6) {
            int k = tid / 6, j = tid % 6;
            int sj = sel[k];
            float v = (j < 3) ? pv[sj*3 + j] : (spts[sj*3 + (j-3)] - anchor[j-3]);
            g_feats[(base + k)*C0 + j] = v;
        }
        if (tid == 0) {
            int s0 = sel[0];
            cur[0] = spts[s0*3+0]; cur[1] = spts[s0*3+1]; cur[2] = spts[s0*3+2];
        }
        __syncthreads();
    }
}

// ---------------- layer 0 (6 -> 64) with per-block BN partials ----------------
__global__ __launch_bounds__(256) void mlp0_kernel(const float* __restrict__ w,
                                                   const float* __restrict__ bias)
{
    __shared__ float sf[64][C0];
    __shared__ float sw[C1*C0];
    __shared__ float sb[C1];
    __shared__ float2 red[4][C1];
    int tid = threadIdx.y*64 + threadIdx.x;
    int p0 = blockIdx.x * 64;
    for (int e = tid; e < 64*C0; e += 256) sf[e/C0][e%C0] = g_feats[(size_t)p0*C0 + e];
    for (int e = tid; e < C1*C0; e += 256) sw[e] = w[e];
    if (tid < C1) sb[tid] = bias[tid];
    __syncthreads();
    int c = threadIdx.x;
    float lw[C0];
    #pragma unroll
    for (int j = 0; j < C0; j++) lw[j] = sw[c*C0+j];
    float bsv = sb[c];
    float lsum = 0.f, lsq = 0.f;
    for (int pi = threadIdx.y; pi < 64; pi += 4) {
        float acc = bsv;
        #pragma unroll
        for (int j = 0; j < C0; j++) acc += sf[pi][j]*lw[j];
        g_h0[(size_t)(p0+pi)*C1 + c] = acc;
        lsum += acc; lsq += acc*acc;
    }
    red[threadIdx.y][c] = make_float2(lsum, lsq);
    __syncthreads();
    if (threadIdx.y == 0) {
        float s = 0.f, q = 0.f;
        #pragma unroll
        for (int r = 0; r < 4; r++) { s += red[r][c].x; q += red[r][c].y; }
        g_pA[blockIdx.x*C1 + c] = s;
        g_pB[blockIdx.x*C1 + c] = q;
    }
}

// ---------------- fold BN stats into scale/shift (deterministic, double acc) -----
__global__ void fold_kernel(int nblk, int C, float cnt,
                            const float* __restrict__ g, const float* __restrict__ be,
                            int slot)
{
    int c = threadIdx.x;
    if (c >= C) return;
    double s = 0.0, q = 0.0;
    for (int r = 0; r < nblk; r++) { s += (double)g_pA[r*C + c]; q += (double)g_pB[r*C + c]; }
    double m = s / (double)cnt;
    double v = q / (double)cnt - m*m;
    float sc = g[c] * rsqrtf((float)v + EPSV);
    g_scale[slot*256 + c] = sc;
    g_shift[slot*256 + c] = be[c] - (float)m * sc;
}

// ---------------- generic tiled SGEMM: out[p,o] = bias[o] + sum_c act(A[p,c])*W[o,c]
// act = relu(affine) folded from previous layer's BN (affSlot >= 0), else identity.
// maxpool==1: instead of storing raw [P,Cout], max-pools groups of 16 consecutive
// rows (the k dimension) and stores [P/16, Cout]. BN partials always on pre-max raw.
__global__ __launch_bounds__(256) void gemm_kernel(
    const float* __restrict__ A, const float* __restrict__ W,
    const float* __restrict__ bias,
    int Cin, int Cout, int affSlot, int maxpool,
    float* __restrict__ out, float* __restrict__ pA, float* __restrict__ pB)
{
    __shared__ __align__(16) float As[BK][BM+PAD];
    __shared__ __align__(16) float Ws[BK][BN+PAD];
    __shared__ float sS[256], sC[256];
    int tid = threadIdx.x;
    int tx = tid & 15, ty = tid >> 4;
    int rowBase = blockIdx.x * BM;
    int colBase = blockIdx.y * BN;
    bool aff = (affSlot >= 0);
    if (aff) {
        for (int e = tid; e < Cin; e += 256) {
            sS[e] = g_scale[affSlot*256 + e];
            sC[e] = g_shift[affSlot*256 + e];
        }
    }
    float acc[8][8] = {};
    for (int k0 = 0; k0 < Cin; k0 += BK) {
        __syncthreads();
        #pragma unroll
        for (int i = 0; i < 4; i++) {
            int f4 = tid + i*256;
            int row = f4 >> 3, kq = (f4 & 7)*4;
            float4 v = *(const float4*)&A[(size_t)(rowBase+row)*Cin + k0 + kq];
            if (aff) {
                v.x = fmaxf(v.x*sS[k0+kq+0] + sC[k0+kq+0], 0.f);
                v.y = fmaxf(v.y*sS[k0+kq+1] + sC[k0+kq+1], 0.f);
                v.z = fmaxf(v.z*sS[k0+kq+2] + sC[k0+kq+2], 0.f);
                v.w = fmaxf(v.w*sS[k0+kq+3] + sC[k0+kq+3], 0.f);
            }
            As[kq+0][row] = v.x; As[kq+1][row] = v.y;
            As[kq+2][row] = v.z; As[kq+3][row] = v.w;
            float4 wv = *(const float4*)&W[(size_t)(colBase+row)*Cin + k0 + kq];
            Ws[kq+0][row] = wv.x; Ws[kq+1][row] = wv.y;
            Ws[kq+2][row] = wv.z; Ws[kq+3][row] = wv.w;
        }
        __syncthreads();
        #pragma unroll
        for (int kk = 0; kk < BK; kk++) {
            float a[8], bw[8];
            *(float4*)&a[0]  = *(float4*)&As[kk][ty*8];
            *(float4*)&a[4]  = *(float4*)&As[kk][ty*8+4];
            *(float4*)&bw[0] = *(float4*)&Ws[kk][tx*8];
            *(float4*)&bw[4] = *(float4*)&Ws[kk][tx*8+4];
            #pragma unroll
            for (int i = 0; i < 8; i++)
                #pragma unroll
                for (int j = 0; j < 8; j++) acc[i][j] += a[i]*bw[j];
        }
    }
    __syncthreads();
    // bias (before BN stats, matching reference)
    float bb[8];
    #pragma unroll
    for (int j = 0; j < 8; j++) bb[j] = bias[colBase + tx*8 + j];
    #pragma unroll
    for (int i = 0; i < 8; i++)
        #pragma unroll
        for (int j = 0; j < 8; j++) acc[i][j] += bb[j];
    // BN partials: reduce over the 128 rows of this tile (alias As as float2 buffer)
    float2* red = (float2*)&As[0][0];
    #pragma unroll
    for (int j = 0; j < 8; j++) {
        float s = 0.f, q = 0.f;
        #pragma unroll
        for (int i = 0; i < 8; i++) { s += acc[i][j]; q += acc[i][j]*acc[i][j]; }
        red[ty*BN + tx*8 + j] = make_float2(s, q);
    }
    __syncthreads();
    if (tid < BN) {
        float s = 0.f, q = 0.f;
        for (int r = 0; r < 16; r++) { float2 v = red[r*BN + tid]; s += v.x; q += v.y; }
        pA[blockIdx.x * Cout + colBase + tid] = s;
        pB[blockIdx.x * Cout + colBase + tid] = q;
    }
    if (!maxpool) {
        #pragma unroll
        for (int i = 0; i < 8; i++) {
            size_t o = (size_t)(rowBase + ty*8 + i)*Cout + colBase + tx*8;
            *(float4*)&out[o]   = make_float4(acc[i][0],acc[i][1],acc[i][2],acc[i][3]);
            *(float4*)&out[o+4] = make_float4(acc[i][4],acc[i][5],acc[i][6],acc[i][7]);
        }
    } else {
        // rows are (btn, k) with k innermost; 16-row groups = one btn each.
        float* mred = (float*)&Ws[0][0];
        #pragma unroll
        for (int j = 0; j < 8; j++) {
            float m = acc[0][j];
            #pragma unroll
            for (int i = 1; i < 8; i++) m = fmaxf(m, acc[i][j]);
            mred[ty*BN + tx*8 + j] = m;
        }
        __syncthreads();
        if ((ty & 1) == 0) {
            int grow = rowBase/16 + (ty >> 1);
            #pragma unroll
            for (int j = 0; j < 8; j++) {
                float m = fmaxf(mred[ty*BN + tx*8 + j], mred[(ty+1)*BN + tx*8 + j]);
                out[(size_t)grow*Cout + colBase + tx*8 + j] = m;
            }
        }
    }
}

// ---------------- transpose wt [o][c][dt] -> [dt][o][c] ----------------
__global__ void wtT_kernel(const float* __restrict__ wt)
{
    int i = blockIdx.x*blockDim.x + threadIdx.x;
    if (i < 3*C3*C3) {
        int dt = i / (C3*C3);
        int o  = (i / C3) % C3;
        int c  = i % C3;
        g_wtT[i] = wt[(o*C3 + c)*3 + dt];
    }
}

// ---------------- temporal conv (3-tap GEMM) with BN partials ----------------
__global__ __launch_bounds__(256) void tconv_kernel(const float* __restrict__ bias)
{
    __shared__ __align__(16) float As[BK][BM+PAD];
    __shared__ __align__(16) float Ws[BK][BN+PAD];
    __shared__ float sS[C3], sC[C3];
    int tid = threadIdx.x;
    int tx = tid & 15, ty = tid >> 4;
    int r0 = blockIdx.x * BM;
    int colBase = blockIdx.y * BN;
    int b  = r0 / (TOUT*NP);
    int to = (r0 / NP) % TOUT;
    int n0 = r0 % NP;
    for (int e = tid; e < C3; e += 256) { sS[e] = g_scale[2*256 + e]; sC[e] = g_shift[2*256 + e]; }
    float acc[8][8] = {};
    for (int dt = 0; dt < 3; dt++) {
        const float* Abase = g_xm + ((size_t)((b*T_ + to + dt)*NP) + n0)*C3;
        const float* Wd    = g_wtT + (size_t)dt*C3*C3;
        for (int k0 = 0; k0 < C3; k0 += BK) {
            __syncthreads();
            #pragma unroll
            for (int i = 0; i < 4; i++) {
                int f4 = tid + i*256;
                int row = f4 >> 3, kq = (f4 & 7)*4;
                float4 v = *(const float4*)&Abase[(size_t)row*C3 + k0 + kq];
                v.x = fmaxf(v.x*sS[k0+kq+0] + sC[k0+kq+0], 0.f);
                v.y = fmaxf(v.y*sS[k0+kq+1] + sC[k0+kq+1], 0.f);
                v.z = fmaxf(v.z*sS[k0+kq+2] + sC[k0+kq+2], 0.f);
                v.w = fmaxf(v.w*sS[k0+kq+3] + sC[k0+kq+3], 0.f);
                As[kq+0][row] = v.x; As[kq+1][row] = v.y;
                As[kq+2][row] = v.z; As[kq+3][row] = v.w;
                float4 wv = *(const float4*)&Wd[(size_t)(colBase+row)*C3 + k0 + kq];
                Ws[kq+0][row] = wv.x; Ws[kq+1][row] = wv.y;
                Ws[kq+2][row] = wv.z; Ws[kq+3][row] = wv.w;
            }
            __syncthreads();
            #pragma unroll
            for (int kk = 0; kk < BK; kk++) {
                float a[8], bw[8];
                *(float4*)&a[0]  = *(float4*)&As[kk][ty*8];
                *(float4*)&a[4]  = *(float4*)&As[kk][ty*8+4];
                *(float4*)&bw[0] = *(float4*)&Ws[kk][tx*8];
                *(float4*)&bw[4] = *(float4*)&Ws[kk][tx*8+4];
                #pragma unroll
                for (int i = 0; i < 8; i++)
                    #pragma unroll
                    for (int j = 0; j < 8; j++) acc[i][j] += a[i]*bw[j];
            }
        }
    }
    __syncthreads();
    float bb[8];
    #pragma unroll
    for (int j = 0; j < 8; j++) bb[j] = bias[colBase + tx*8 + j];
    #pragma unroll
    for (int i = 0; i < 8; i++)
        #pragma unroll
        for (int j = 0; j < 8; j++) acc[i][j] += bb[j];
    float2* red = (float2*)&As[0][0];
    #pragma unroll
    for (int j = 0; j < 8; j++) {
        float s = 0.f, q = 0.f;
        #pragma unroll
        for (int i = 0; i < 8; i++) { s += acc[i][j]; q += acc[i][j]*acc[i][j]; }
        red[ty*BN + tx*8 + j] = make_float2(s, q);
    }
    __syncthreads();
    if (tid < BN) {
        float s = 0.f, q = 0.f;
        for (int r = 0; r < 16; r++) { float2 v = red[r*BN + tid]; s += v.x; q += v.y; }
        g_pA[blockIdx.x * C3 + colBase + tid] = s;
        g_pB[blockIdx.x * C3 + colBase + tid] = q;
    }
    #pragma unroll
    for (int i = 0; i < 8; i++) {
        size_t o = (size_t)(r0 + ty*8 + i)*C3 + colBase + tx*8;
        *(float4*)&g_y[o]   = make_float4(acc[i][0],acc[i][1],acc[i][2],acc[i][3]);
        *(float4*)&g_y[o+4] = make_float4(acc[i][4],acc[i][5],acc[i][6],acc[i][7]);
    }
}

// ---------------- final BN + relu -> output ----------------
__global__ void final_kernel(float* __restrict__ out)
{
    int i = blockIdx.x*blockDim.x + threadIdx.x;
    if (i < PT*C3) {
        int c = i & 255;
        out[i] = fmaxf(g_y[i]*g_scale[3*256 + c] + g_shift[3*256 + c], 0.f);
    }
}

// ---------------- launch ----------------
extern "C" void kernel_launch(void* const* d_in, const int* in_sizes, int n_in,
                              void* d_out, int out_size)
{
    (void)in_sizes; (void)n_in; (void)out_size;
    const float* pts = (const float*)d_in[0];
    const float* w0  = (const float*)d_in[1];
    const float* b0  = (const float*)d_in[2];
    const float* gg0 = (const float*)d_in[3];
    const float* be0 = (const float*)d_in[4];
    const float* w1  = (const float*)d_in[5];
    const float* b1  = (const float*)d_in[6];
    const float* gg1 = (const float*)d_in[7];
    const float* be1 = (const float*)d_in[8];
    const float* w2  = (const float*)d_in[9];
    const float* b2  = (const float*)d_in[10];
    const float* gg2 = (const float*)d_in[11];
    const float* be2 = (const float*)d_in[12];
    const float* wt  = (const float*)d_in[13];
    const float* bt  = (const float*)d_in[14];
    const float* ggt = (const float*)d_in[15];
    const float* bet = (const float*)d_in[16];
    float* out = (float*)d_out;

    float *dh0 = nullptr, *dh1 = nullptr, *dxm = nullptr, *dpA = nullptr, *dpB = nullptr;
    cudaGetSymbolAddress((void**)&dh0, g_h0);
    cudaGetSymbolAddress((void**)&dh1, g_h1);
    cudaGetSymbolAddress((void**)&dxm, g_xm);
    cudaGetSymbolAddress((void**)&dpA, g_pA);
    cudaGetSymbolAddress((void**)&dpB, g_pB);

    wtT_kernel<<<(3*C3*C3 + 255)/256, 256>>>(wt);
    knn_kernel<<<B_*NP, 128>>>(pts);

    mlp0_kernel<<<P1/64, dim3(64,4)>>>(w0, b0);
    fold_kernel<<<1, C1>>>(P1/64, C1, (float)P1, gg0, be0, 0);

    gemm_kernel<<<dim3(P1/BM, C2/BN), 256>>>(dh0, w1, b1, C1, C2, 0, 0, dh1, dpA, dpB);
    fold_kernel<<<1, C2>>>(P1/BM, C2, (float)P1, gg1, be1, 1);

    gemm_kernel<<<dim3(P1/BM, C3/BN), 256>>>(dh1, w2, b2, C2, C3, 1, 1, dxm, dpA, dpB);
    fold_kernel<<<1, C3>>>(P1/BM, C3, (float)P1, gg2, be2, 2);

    tconv_kernel<<<dim3(PT/BM, C3/BN), 256>>>(bt);
    fold_kernel<<<1, C3>>>(PT/BM, C3, (float)PT, ggt, bet, 3);

    final_kernel<<<(PT*C3 + 255)/256, 256>>>(out);
}

// round 3
// speedup vs baseline: 1.2661x; 1.2661x over previous
#include <cuda_runtime.h>
#include <cuda_bf16.h>
#include <cfloat>
#include <cstdint>
#include <cstddef>

#define B_  2
#define T_  16
#define NP  1024
#define KNN 16
#define TOUT 14
#define C0 6
#define C1 64
#define C2 128
#define C3 256
#define EPSV 1e-5f

#define P1 (B_*T_*NP*KNN)   /* 524288 rows into MLP */
#define PM (B_*T_*NP)       /* 32768 rows after max-k */
#define PT (B_*TOUT*NP)     /* 28672 output rows */

// ---------------- scratch ----------------
__device__ float g_feats[(size_t)P1*C0];
__device__ float g_h0[(size_t)P1*C1];
__device__ float g_h1[(size_t)P1*C2];
__device__ float g_xm[(size_t)PM*C3];
__device__ float g_y[(size_t)PT*C3];
__device__ float g_pA[(P1/128)*C3];
__device__ float g_pB[(P1/128)*C3];
__device__ float g_scale[4*256];
__device__ float g_shift[4*256];
// pre-split, pre-swizzled bf16 weights: per chunk [hi tile N*64][lo tile N*64]
__device__ __nv_bfloat16 g_w1x[1*2*128*64];
__device__ __nv_bfloat16 g_w2x[2*2*256*64];
__device__ __nv_bfloat16 g_wtx[12*2*256*64];

#define SWZ(x) ((x) ^ (((x) >> 3) & 0x70))

__device__ __forceinline__ uint32_t smem_u32(const void* p) {
    uint32_t a;
    asm("{ .reg .u64 t; cvta.to.shared.u64 t, %1; cvt.u32.u64 %0, t; }" : "=r"(a) : "l"(p));
    return a;
}
__device__ __forceinline__ uint32_t pkbf(float a, float b) {
    __nv_bfloat162 h = __floats2bfloat162_rn(a, b);
    return *reinterpret_cast<uint32_t*>(&h);
}
__device__ __forceinline__ void ldm_x4(uint32_t addr, uint32_t& r0, uint32_t& r1,
                                       uint32_t& r2, uint32_t& r3) {
    asm volatile("ldmatrix.sync.aligned.m8n8.x4.shared.b16 {%0,%1,%2,%3}, [%4];"
                 : "=r"(r0), "=r"(r1), "=r"(r2), "=r"(r3) : "r"(addr));
}
__device__ __forceinline__ void mma16816(float* d, const uint32_t* a, const uint32_t* b) {
    asm volatile("mma.sync.aligned.m16n8k16.row.col.f32.bf16.bf16.f32 "
        "{%0,%1,%2,%3}, {%4,%5,%6,%7}, {%8,%9}, {%0,%1,%2,%3};"
        : "+f"(d[0]), "+f"(d[1]), "+f"(d[2]), "+f"(d[3])
        : "r"(a[0]), "r"(a[1]), "r"(a[2]), "r"(a[3]), "r"(b[0]), "r"(b[1]));
}
__device__ __forceinline__ float shfl_sum3(float v) {
    v += __shfl_xor_sync(0xffffffffu, v, 4);
    v += __shfl_xor_sync(0xffffffffu, v, 8);
    v += __shfl_xor_sync(0xffffffffu, v, 16);
    return v;
}
__device__ __forceinline__ float shfl_max3(float v) {
    v = fmaxf(v, __shfl_xor_sync(0xffffffffu, v, 4));
    v = fmaxf(v, __shfl_xor_sync(0xffffffffu, v, 8));
    v = fmaxf(v, __shfl_xor_sync(0xffffffffu, v, 16));
    return v;
}

// ---------------- stage 1: KNN trajectory + feature extraction ----------------
__global__ __launch_bounds__(128) void knn_kernel(const float* __restrict__ pts)
{
    __shared__ float spts[NP*3];
    __shared__ float d2s[NP];
    __shared__ float cur[3];
    __shared__ float anchor[3];
    __shared__ int   sel[KNN];
    __shared__ float wv[4];
    __shared__ int   wj[4];

    int b = blockIdx.x / NP;
    int i = blockIdx.x % NP;
    int tid = threadIdx.x;
    int lane = tid & 31, wid = tid >> 5;

    if (tid < 3) cur[tid] = pts[((size_t)(b*T_ + 0)*NP + i)*3 + tid];

    for (int t = 0; t < T_; t++) {
        const float* pt = pts + (size_t)(b*T_ + t)*NP*3;
        const float* pv = pts + (size_t)(b*T_ + (t == 0 ? 0 : t-1))*NP*3;
        for (int e = tid; e < NP*3; e += 128) spts[e] = pt[e];
        __syncthreads();
        float cx = cur[0], cy = cur[1], cz = cur[2];
        for (int j = tid; j < NP; j += 128) {
            float dx = cx - spts[j*3+0];
            float dy = cy - spts[j*3+1];
            float dz = cz - spts[j*3+2];
            d2s[j] = dx*dx + dy*dy + dz*dz;
        }
        __syncthreads();
        for (int k = 0; k < KNN; k++) {
            float bv = FLT_MAX; int bj = NP;
            for (int j = tid; j < NP; j += 128) {
                float v = d2s[j];
                if (v < bv) { bv = v; bj = j; }
            }
            #pragma unroll
            for (int off = 16; off; off >>= 1) {
                float ov = __shfl_down_sync(0xffffffffu, bv, off);
                int   oj = __shfl_down_sync(0xffffffffu, bj, off);
                if (ov < bv || (ov == bv && oj < bj)) { bv = ov; bj = oj; }
            }
            if (lane == 0) { wv[wid] = bv; wj[wid] = bj; }
            __syncthreads();
            if (tid == 0) {
                float mv = wv[0]; int mj = wj[0];
                for (int w = 1; w < 4; w++)
                    if (wv[w] < mv || (wv[w] == mv && wj[w] < mj)) { mv = wv[w]; mj = wj[w]; }
                sel[k] = mj;
                d2s[mj] = FLT_MAX;
                if (k == 0 && t == 0) {
                    anchor[0] = spts[mj*3+0];
                    anchor[1] = spts[mj*3+1];
                    anchor[2] = spts[mj*3+2];
                }
            }
            __syncthreads();
        }
        size_t base = ((size_t)((b*T_ + t)*NP) + i) * KNN;
        if (tid < KNN*6) {
            int k = tid / 6, j = tid % 6;
            int sj = sel[k];
            float v = (j < 3) ? pv[sj*3 + j] : (spts[sj*3 + (j-3)] - anchor[j-3]);
            g_feats[(base + k)*C0 + j] = v;
        }
        if (tid == 0) {
            int s0 = sel[0];
            cur[0] = spts[s0*3+0]; cur[1] = spts[s0*3+1]; cur[2] = spts[s0*3+2];
        }
        __syncthreads();
    }
}

// ---------------- layer 0 (6 -> 64) with per-block BN partials ----------------
__global__ __launch_bounds__(256) void mlp0_kernel(const float* __restrict__ w,
                                                   const float* __restrict__ bias)
{
    __shared__ float sf[64][C0];
    __shared__ float sw[C1*C0];
    __shared__ float sb[C1];
    __shared__ float2 red[4][C1];
    int tid = threadIdx.y*64 + threadIdx.x;
    int p0 = blockIdx.x * 64;
    for (int e = tid; e < 64*C0; e += 256) sf[e/C0][e%C0] = g_feats[(size_t)p0*C0 + e];
    for (int e = tid; e < C1*C0; e += 256) sw[e] = w[e];
    if (tid < C1) sb[tid] = bias[tid];
    __syncthreads();
    int c = threadIdx.x;
    float lw[C0];
    #pragma unroll
    for (int j = 0; j < C0; j++) lw[j] = sw[c*C0+j];
    float bsv = sb[c];
    float lsum = 0.f, lsq = 0.f;
    for (int pi = threadIdx.y; pi < 64; pi += 4) {
        float acc = bsv;
        #pragma unroll
        for (int j = 0; j < C0; j++) acc += sf[pi][j]*lw[j];
        g_h0[(size_t)(p0+pi)*C1 + c] = acc;
        lsum += acc; lsq += acc*acc;
    }
    red[threadIdx.y][c] = make_float2(lsum, lsq);
    __syncthreads();
    if (threadIdx.y == 0) {
        float s = 0.f, q = 0.f;
        #pragma unroll
        for (int r = 0; r < 4; r++) { s += red[r][c].x; q += red[r][c].y; }
        g_pA[blockIdx.x*C1 + c] = s;
        g_pB[blockIdx.x*C1 + c] = q;
    }
}

// ---------------- fold BN stats into scale/shift ----------------
__global__ void fold_kernel(int nblk, int C, float cnt,
                            const float* __restrict__ g, const float* __restrict__ be,
                            int slot)
{
    int c = threadIdx.x;
    if (c >= C) return;
    double s = 0.0, q = 0.0;
    for (int r = 0; r < nblk; r++) { s += (double)g_pA[r*C + c]; q += (double)g_pB[r*C + c]; }
    double m = s / (double)cnt;
    double v = q / (double)cnt - m*m;
    float sc = g[c] * rsqrtf((float)v + EPSV);
    g_scale[slot*256 + c] = sc;
    g_shift[slot*256 + c] = be[c] - (float)m * sc;
}

// ---------------- weight prep: fp32 -> bf16 hi/lo, pre-swizzled tile images ----
__global__ void prepw_kernel(const float* __restrict__ W, int N, int Cin,
                             __nv_bfloat16* __restrict__ dst)
{
    int i = blockIdx.x*256 + threadIdx.x;
    if (i >= N*Cin) return;
    int n = i / Cin, c = i % Cin;
    int chunk = c >> 6, k = c & 63;
    float w = W[i];
    __nv_bfloat16 h = __float2bfloat16_rn(w);
    float lo = w - __bfloat162float(h);
    int off = SWZ(n*128 + k*2) >> 1;
    size_t base = (size_t)chunk * (2*N*64);
    dst[base + off] = h;
    dst[base + N*64 + off] = __float2bfloat16_rn(lo);
}

__global__ void prepwt_kernel(const float* __restrict__ wt)
{
    int i = blockIdx.x*256 + threadIdx.x;
    if (i >= C3*C3*3) return;
    int dt = i % 3;
    int c  = (i / 3) % C3;
    int o  = i / (3*C3);
    int chunk = dt*4 + (c >> 6);
    int k = c & 63;
    float w = wt[i];
    __nv_bfloat16 h = __float2bfloat16_rn(w);
    float lo = w - __bfloat162float(h);
    int off = SWZ(o*128 + k*2) >> 1;
    size_t base = (size_t)chunk * (2*C3*64);
    g_wtx[base + off] = h;
    g_wtx[base + C3*64 + off] = __float2bfloat16_rn(lo);
}

// ---------------- HMMA GEMM (split-bf16 x3 emulation of fp32) ----------------
// CTA tile: 128 rows x 128 cols. 8 warps: warpRow = wid&1 (64 rows), warpCol =
// wid>>1 (32 cols). Per warp: 4 m16 tiles x 4 n8 tiles, f32 accum.
// MODE 0: raw out.  MODE 1: k-maxpool out (16-row groups).  MODE 2: tconv A
// addressing (12 chunks = 3 dt x 4 kc), raw out.
template<int CIN, int COUT, int NCHUNK, int MODE>
__global__ __launch_bounds__(256) void mma_gemm(
    const float* __restrict__ A, const __nv_bfloat16* __restrict__ Wx,
    const float* __restrict__ bias, int affSlot,
    float* __restrict__ out, float* __restrict__ pA, float* __restrict__ pB)
{
    extern __shared__ __align__(1024) char smem[];
    constexpr int OFF_AHI = 0;
    constexpr int OFF_ALO = 16384;
    constexpr int OFF_WHI = 32768;
    constexpr int OFF_WLO = 49152;
    constexpr int OFF_BIAS = 65536;           // 128 f32
    constexpr int OFF_SS  = 66048;            // 256 f32
    constexpr int OFF_SC  = 67072;            // 256 f32
    constexpr int OFF_PS  = 68096;            // 2*128 f32
    constexpr int OFF_PQ  = 69120;            // 2*128 f32

    const int tid = threadIdx.x;
    const int wid = tid >> 5, lane = tid & 31;
    const int warpRow = wid & 1, warpCol = wid >> 1;
    const int rowBase = blockIdx.x * 128;
    const int colBase = blockIdx.y * 128;
    const uint32_t sb32 = smem_u32(smem);

    float* sbias = (float*)(smem + OFF_BIAS);
    float* sS = (float*)(smem + OFF_SS);
    float* sC = (float*)(smem + OFF_SC);
    if (tid < 128) sbias[tid] = bias[colBase + tid];
    for (int e = tid; e < CIN; e += 256) {
        sS[e] = g_scale[affSlot*256 + e];
        sC[e] = g_shift[affSlot*256 + e];
    }

    int bb = 0, to = 0, n0 = 0;
    if (MODE == 2) { bb = rowBase/(TOUT*NP); to = (rowBase/NP) % TOUT; n0 = rowBase % NP; }

    float acc[4][4][4] = {};

    for (int chunk = 0; chunk < NCHUNK; chunk++) {
        const float* Ab; int cs, chBase;
        if (MODE == 2) {
            int dt = chunk >> 2, kc = chunk & 3;
            Ab = A + ((size_t)((bb*T_ + to + dt)*NP + n0))*C3 + kc*64;
            cs = C3; chBase = kc*64;
        } else {
            Ab = A + (size_t)rowBase*CIN + chunk*64;
            cs = CIN; chBase = chunk*64;
        }
        __syncthreads();
        // A: fp32 load -> affine+relu -> split bf16 hi/lo -> swizzled smem
        #pragma unroll
        for (int i = 0; i < 8; i++) {
            int f = tid + i*256;
            int row = f >> 4;
            int k = (f & 15) * 4;
            float4 v = *(const float4*)(Ab + (size_t)row*cs + k);
            int ch = chBase + k;
            v.x = fmaxf(fmaf(v.x, sS[ch+0], sC[ch+0]), 0.f);
            v.y = fmaxf(fmaf(v.y, sS[ch+1], sC[ch+1]), 0.f);
            v.z = fmaxf(fmaf(v.z, sS[ch+2], sC[ch+2]), 0.f);
            v.w = fmaxf(fmaf(v.w, sS[ch+3], sC[ch+3]), 0.f);
            float h0 = __bfloat162float(__float2bfloat16_rn(v.x));
            float h1 = __bfloat162float(__float2bfloat16_rn(v.y));
            float h2 = __bfloat162float(__float2bfloat16_rn(v.z));
            float h3 = __bfloat162float(__float2bfloat16_rn(v.w));
            uint32_t off = SWZ((uint32_t)(row*128 + k*2));
            *(uint32_t*)(smem + OFF_AHI + off)     = pkbf(v.x, v.y);
            *(uint32_t*)(smem + OFF_AHI + off + 4) = pkbf(v.z, v.w);
            *(uint32_t*)(smem + OFF_ALO + off)     = pkbf(v.x - h0, v.y - h1);
            *(uint32_t*)(smem + OFF_ALO + off + 4) = pkbf(v.z - h2, v.w - h3);
        }
        // W subtile copy (pre-swizzled image): 128 n-rows x 64 k, hi + lo
        {
            const float4* srcH = (const float4*)(Wx + (size_t)chunk*2*((size_t)COUT*64) + (size_t)colBase*64);
            const float4* srcL = (const float4*)(Wx + (size_t)chunk*2*((size_t)COUT*64) + (size_t)COUT*64 + (size_t)colBase*64);
            float4* dH = (float4*)(smem + OFF_WHI);
            float4* dL = (float4*)(smem + OFF_WLO);
            #pragma unroll
            for (int i = 0; i < 4; i++) { dH[tid + i*256] = srcH[tid + i*256]; dL[tid + i*256] = srcL[tid + i*256]; }
        }
        __syncthreads();
        // compute: 4 k16 steps
        #pragma unroll
        for (int ks = 0; ks < 4; ks++) {
            uint32_t bh[4][2], bl[4][2];
            #pragma unroll
            for (int nt2 = 0; nt2 < 2; nt2++) {
                uint32_t roff = (uint32_t)((warpCol*32 + nt2*16 + ((lane>>4)<<3) + (lane&7))*128
                                           + ks*32 + (((lane>>3)&1)<<4));
                uint32_t ah = sb32 + OFF_WHI + SWZ(roff);
                uint32_t al = sb32 + OFF_WLO + SWZ(roff);
                ldm_x4(ah, bh[nt2*2][0], bh[nt2*2][1], bh[nt2*2+1][0], bh[nt2*2+1][1]);
                ldm_x4(al, bl[nt2*2][0], bl[nt2*2][1], bl[nt2*2+1][0], bl[nt2*2+1][1]);
            }
            #pragma unroll
            for (int mt = 0; mt < 4; mt++) {
                uint32_t roff = (uint32_t)((warpRow*64 + mt*16 + (lane&15))*128
                                           + ks*32 + ((lane>>4)<<4));
                uint32_t ahreg[4], alreg[4];
                ldm_x4(sb32 + OFF_AHI + SWZ(roff), ahreg[0], ahreg[1], ahreg[2], ahreg[3]);
                ldm_x4(sb32 + OFF_ALO + SWZ(roff), alreg[0], alreg[1], alreg[2], alreg[3]);
                #pragma unroll
                for (int nt = 0; nt < 4; nt++) mma16816(acc[mt][nt], ahreg, bh[nt]);
                #pragma unroll
                for (int nt = 0; nt < 4; nt++) mma16816(acc[mt][nt], ahreg, bl[nt]);
                #pragma unroll
                for (int nt = 0; nt < 4; nt++) mma16816(acc[mt][nt], alreg, bh[nt]);
            }
        }
    }

    // -------- epilogue --------
    // bias add (before BN stats, matching reference)
    #pragma unroll
    for (int nt = 0; nt < 4; nt++) {
        int cl = warpCol*32 + nt*8 + (lane&3)*2;
        float b0 = sbias[cl], b1 = sbias[cl+1];
        #pragma unroll
        for (int mt = 0; mt < 4; mt++) {
            acc[mt][nt][0] += b0; acc[mt][nt][1] += b1;
            acc[mt][nt][2] += b0; acc[mt][nt][3] += b1;
        }
    }
    // BN partials: per-column sum & sumsq over the warp's 64 rows
    float* ps = (float*)(smem + OFF_PS);
    float* pq = (float*)(smem + OFF_PQ);
    #pragma unroll
    for (int nt = 0; nt < 4; nt++) {
        float s0 = 0.f, s1 = 0.f, q0 = 0.f, q1 = 0.f;
        #pragma unroll
        for (int mt = 0; mt < 4; mt++) {
            float c0 = acc[mt][nt][0], c1 = acc[mt][nt][1];
            float c2 = acc[mt][nt][2], c3 = acc[mt][nt][3];
            s0 += c0 + c2; s1 += c1 + c3;
            q0 += c0*c0 + c2*c2; q1 += c1*c1 + c3*c3;
        }
        s0 = shfl_sum3(s0); s1 = shfl_sum3(s1);
        q0 = shfl_sum3(q0); q1 = shfl_sum3(q1);
        if (lane < 4) {
            int cl = warpCol*32 + nt*8 + lane*2;
            ps[warpRow*128 + cl] = s0; ps[warpRow*128 + cl + 1] = s1;
            pq[warpRow*128 + cl] = q0; pq[warpRow*128 + cl + 1] = q1;
        }
    }
    // outputs
    if (MODE == 1) {
        // each m16 tile == one 16-row pool group
        #pragma unroll
        for (int mt = 0; mt < 4; mt++) {
            int grow = (rowBase >> 4) + warpRow*4 + mt;
            #pragma unroll
            for (int nt = 0; nt < 4; nt++) {
                float m0 = shfl_max3(fmaxf(acc[mt][nt][0], acc[mt][nt][2]));
                float m1 = shfl_max3(fmaxf(acc[mt][nt][1], acc[mt][nt][3]));
                if (lane < 4) {
                    int cl = colBase + warpCol*32 + nt*8 + lane*2;
                    *(float2*)&out[(size_t)grow*COUT + cl] = make_float2(m0, m1);
                }
            }
        }
    } else {
        #pragma unroll
        for (int mt = 0; mt < 4; mt++) {
            int r0 = rowBase + warpRow*64 + mt*16 + (lane >> 2);
            #pragma unroll
            for (int nt = 0; nt < 4; nt++) {
                int cl = colBase + warpCol*32 + nt*8 + (lane&3)*2;
                *(float2*)&out[(size_t)r0*COUT + cl]     = make_float2(acc[mt][nt][0], acc[mt][nt][1]);
                *(float2*)&out[(size_t)(r0+8)*COUT + cl] = make_float2(acc[mt][nt][2], acc[mt][nt][3]);
            }
        }
    }
    __syncthreads();
    if (tid < 128) {
        pA[(size_t)blockIdx.x*COUT + colBase + tid] = ps[tid] + ps[128 + tid];
        pB[(size_t)blockIdx.x*COUT + colBase + tid] = pq[tid] + pq[128 + tid];
    }
}

// ---------------- final BN + relu -> output ----------------
__global__ void final_kernel(float* __restrict__ out)
{
    int i = blockIdx.x*blockDim.x + threadIdx.x;
    if (i < PT*C3) {
        int c = i & 255;
        out[i] = fmaxf(g_y[i]*g_scale[3*256 + c] + g_shift[3*256 + c], 0.f);
    }
}

// ---------------- launch ----------------
extern "C" void kernel_launch(void* const* d_in, const int* in_sizes, int n_in,
                              void* d_out, int out_size)
{
    (void)in_sizes; (void)n_in; (void)out_size;
    const float* pts = (const float*)d_in[0];
    const float* w0  = (const float*)d_in[1];
    const float* b0  = (const float*)d_in[2];
    const float* gg0 = (const float*)d_in[3];
    const float* be0 = (const float*)d_in[4];
    const float* w1  = (const float*)d_in[5];
    const float* b1  = (const float*)d_in[6];
    const float* gg1 = (const float*)d_in[7];
    const float* be1 = (const float*)d_in[8];
    const float* w2  = (const float*)d_in[9];
    const float* b2  = (const float*)d_in[10];
    const float* gg2 = (const float*)d_in[11];
    const float* be2 = (const float*)d_in[12];
    const float* wt  = (const float*)d_in[13];
    const float* bt  = (const float*)d_in[14];
    const float* ggt = (const float*)d_in[15];
    const float* bet = (const float*)d_in[16];
    float* out = (float*)d_out;

    float *dh0 = nullptr, *dh1 = nullptr, *dxm = nullptr, *dy = nullptr;
    float *dpA = nullptr, *dpB = nullptr;
    __nv_bfloat16 *dw1x = nullptr, *dw2x = nullptr, *dwtx = nullptr;
    cudaGetSymbolAddress((void**)&dh0, g_h0);
    cudaGetSymbolAddress((void**)&dh1, g_h1);
    cudaGetSymbolAddress((void**)&dxm, g_xm);
    cudaGetSymbolAddress((void**)&dy, g_y);
    cudaGetSymbolAddress((void**)&dpA, g_pA);
    cudaGetSymbolAddress((void**)&dpB, g_pB);
    cudaGetSymbolAddress((void**)&dw1x, g_w1x);
    cudaGetSymbolAddress((void**)&dw2x, g_w2x);
    cudaGetSymbolAddress((void**)&dwtx, g_wtx);

    const int SMB = 70144;
    static bool attr_set = false;
    if (!attr_set) {
        cudaFuncSetAttribute(mma_gemm<64,128,1,0>,   cudaFuncAttributeMaxDynamicSharedMemorySize, SMB);
        cudaFuncSetAttribute(mma_gemm<128,256,2,1>,  cudaFuncAttributeMaxDynamicSharedMemorySize, SMB);
        cudaFuncSetAttribute(mma_gemm<256,256,12,2>, cudaFuncAttributeMaxDynamicSharedMemorySize, SMB);
        attr_set = true;
    }

    prepw_kernel<<<(C2*C1 + 255)/256, 256>>>(w1, C2, C1, dw1x);
    prepw_kernel<<<(C3*C2 + 255)/256, 256>>>(w2, C3, C2, dw2x);
    prepwt_kernel<<<(C3*C3*3 + 255)/256, 256>>>(wt);
    knn_kernel<<<B_*NP, 128>>>(pts);

    mlp0_kernel<<<P1/64, dim3(64,4)>>>(w0, b0);
    fold_kernel<<<1, C1>>>(P1/64, C1, (float)P1, gg0, be0, 0);

    mma_gemm<64,128,1,0><<<dim3(P1/128, 1), 256, SMB>>>(dh0, dw1x, b1, 0, dh1, dpA, dpB);
    fold_kernel<<<1, C2>>>(P1/128, C2, (float)P1, gg1, be1, 1);

    mma_gemm<128,256,2,1><<<dim3(P1/128, 2), 256, SMB>>>(dh1, dw2x, b2, 1, dxm, dpA, dpB);
    fold_kernel<<<1, C3>>>(P1/128, C3, (float)P1, gg2, be2, 2);

    mma_gemm<256,256,12,2><<<dim3(PT/128, 2), 256, SMB>>>(dxm, dwtx, bt, 2, dy, dpA, dpB);
    fold_kernel<<<1, C3>>>(PT/128, C3, (float)PT, ggt, bet, 3);

    final_kernel<<<(PT*C3 + 255)/256, 256>>>(out);
}

// round 5
// speedup vs baseline: 1.3815x; 1.0912x over previous
#include <cuda_runtime.h>
#include <cuda_bf16.h>
#include <cfloat>
#include <cstdint>
#include <cstddef>

#define B_  2
#define T_  16
#define NP  1024
#define KNN 16
#define TOUT 14
#define C0 6
#define C1 64
#define C2 128
#define C3 256
#define EPSV 1e-5f

#define P1 (B_*T_*NP*KNN)
#define PM (B_*T_*NP)
#define PT (B_*TOUT*NP)

// ---------------- scratch ----------------
__device__ float g_feats[(size_t)P1*C0];
__device__ float g_h0[(size_t)P1*C1];
__device__ float g_h1[(size_t)P1*C2];
__device__ float g_xm[(size_t)PM*C3];
__device__ float g_y[(size_t)PT*C3];
__device__ float g_pA[(P1/128)*C3];
__device__ float g_pB[(P1/128)*C3];
__device__ float g_scale[4*256];
__device__ float g_shift[4*256];
__device__ __nv_bfloat16 g_w1x[1*2*128*64];
__device__ __nv_bfloat16 g_w2x[2*2*256*64];
__device__ __nv_bfloat16 g_wtx[12*2*256*64];

#define SWZ(x) ((x) ^ (((x) >> 3) & 0x70))

__device__ __forceinline__ uint32_t smem_u32(const void* p) {
    uint32_t a;
    asm("{ .reg .u64 t; cvta.to.shared.u64 t, %1; cvt.u32.u64 %0, t; }" : "=r"(a) : "l"(p));
    return a;
}
__device__ __forceinline__ uint32_t pkbf(float a, float b) {
    __nv_bfloat162 h = __floats2bfloat162_rn(a, b);
    return *reinterpret_cast<uint32_t*>(&h);
}
__device__ __forceinline__ void ldm_x4(uint32_t addr, uint32_t& r0, uint32_t& r1,
                                       uint32_t& r2, uint32_t& r3) {
    asm volatile("ldmatrix.sync.aligned.m8n8.x4.shared.b16 {%0,%1,%2,%3}, [%4];"
                 : "=r"(r0), "=r"(r1), "=r"(r2), "=r"(r3) : "r"(addr));
}
__device__ __forceinline__ void mma16816(float* d, const uint32_t* a, const uint32_t* b) {
    asm volatile("mma.sync.aligned.m16n8k16.row.col.f32.bf16.bf16.f32 "
        "{%0,%1,%2,%3}, {%4,%5,%6,%7}, {%8,%9}, {%0,%1,%2,%3};"
        : "+f"(d[0]), "+f"(d[1]), "+f"(d[2]), "+f"(d[3])
        : "r"(a[0]), "r"(a[1]), "r"(a[2]), "r"(a[3]), "r"(b[0]), "r"(b[1]));
}
__device__ __forceinline__ void cpasync16(uint32_t saddr, const void* g) {
    asm volatile("cp.async.cg.shared.global [%0], [%1], 16;" :: "r"(saddr), "l"(g));
}
#define CP_COMMIT() asm volatile("cp.async.commit_group;" ::: "memory")
#define CP_WAIT(n)  asm volatile("cp.async.wait_group %0;" :: "n"(n) : "memory")

__device__ __forceinline__ float shfl_sum3(float v) {
    v += __shfl_xor_sync(0xffffffffu, v, 4);
    v += __shfl_xor_sync(0xffffffffu, v, 8);
    v += __shfl_xor_sync(0xffffffffu, v, 16);
    return v;
}
__device__ __forceinline__ float shfl_max3(float v) {
    v = fmaxf(v, __shfl_xor_sync(0xffffffffu, v, 4));
    v = fmaxf(v, __shfl_xor_sync(0xffffffffu, v, 8));
    v = fmaxf(v, __shfl_xor_sync(0xffffffffu, v, 16));
    return v;
}

// ---------------- stage 1: KNN, warp-per-trajectory ----------------
__global__ __launch_bounds__(128) void knn_kernel(const float* __restrict__ pts)
{
    __shared__ float spts[NP*3];      // 12 KB, shared by 4 warps (same b)
    __shared__ float d2w[4][NP];      // 16 KB
    __shared__ int   selw[4][KNN];

    int tid = threadIdx.x;
    int w = tid >> 5, lane = tid & 31;
    int gid = blockIdx.x*4 + w;       // trajectory id
    int b = gid >> 10, i = gid & 1023;

    float cx = pts[((size_t)(b*T_)*NP + i)*3 + 0];
    float cy = pts[((size_t)(b*T_)*NP + i)*3 + 1];
    float cz = pts[((size_t)(b*T_)*NP + i)*3 + 2];
    float ax = 0.f, ay = 0.f, az = 0.f;

    for (int t = 0; t < T_; t++) {
        const float* pt = pts + (size_t)(b*T_ + t)*NP*3;
        const float* pv = pts + (size_t)(b*T_ + (t == 0 ? 0 : t-1))*NP*3;
        for (int e = tid; e < NP*3; e += 128) spts[e] = pt[e];
        __syncthreads();
        for (int j = lane; j < NP; j += 32) {
            float dx = cx - spts[j*3+0];
            float dy = cy - spts[j*3+1];
            float dz = cz - spts[j*3+2];
            d2w[w][j] = dx*dx + dy*dy + dz*dz;
        }
        __syncwarp();
        for (int k = 0; k < KNN; k++) {
            float bv = FLT_MAX; int bj = NP;
            #pragma unroll
            for (int m = 0; m < NP/32; m++) {
                int j = lane + m*32;
                float v = d2w[w][j];
                if (v < bv) { bv = v; bj = j; }
            }
            #pragma unroll
            for (int off = 16; off; off >>= 1) {
                float ov = __shfl_xor_sync(0xffffffffu, bv, off);
                int   oj = __shfl_xor_sync(0xffffffffu, bj, off);
                if (ov < bv || (ov == bv && oj < bj)) { bv = ov; bj = oj; }
            }
            if (lane == 0) { selw[w][k] = bj; d2w[w][bj] = FLT_MAX; }
            __syncwarp();
            if (k == 0 && t == 0) {
                ax = spts[bj*3+0]; ay = spts[bj*3+1]; az = spts[bj*3+2];
            }
        }
        size_t basef = ((size_t)((b*T_ + t)*NP) + i) * KNN;
        if (lane < KNN) {
            int sj = selw[w][lane];
            float* dst = g_feats + (basef + lane)*6;
            dst[0] = pv[sj*3+0]; dst[1] = pv[sj*3+1]; dst[2] = pv[sj*3+2];
            dst[3] = spts[sj*3+0] - ax; dst[4] = spts[sj*3+1] - ay; dst[5] = spts[sj*3+2] - az;
        }
        int s0 = selw[w][0];
        cx = spts[s0*3+0]; cy = spts[s0*3+1]; cz = spts[s0*3+2];
        __syncthreads();
    }
}

// ---------------- layer 0 (6 -> 64) with per-block BN partials ----------------
__global__ __launch_bounds__(256) void mlp0_kernel(const float* __restrict__ w,
                                                   const float* __restrict__ bias)
{
    __shared__ float sf[64][C0];
    __shared__ float sw[C1*C0];
    __shared__ float sb[C1];
    __shared__ float2 red[4][C1];
    int tid = threadIdx.y*64 + threadIdx.x;
    int p0 = blockIdx.x * 64;
    for (int e = tid; e < 64*C0; e += 256) sf[e/C0][e%C0] = g_feats[(size_t)p0*C0 + e];
    for (int e = tid; e < C1*C0; e += 256) sw[e] = w[e];
    if (tid < C1) sb[tid] = bias[tid];
    __syncthreads();
    int c = threadIdx.x;
    float lw[C0];
    #pragma unroll
    for (int j = 0; j < C0; j++) lw[j] = sw[c*C0+j];
    float bsv = sb[c];
    float lsum = 0.f, lsq = 0.f;
    for (int pi = threadIdx.y; pi < 64; pi += 4) {
        float acc = bsv;
        #pragma unroll
        for (int j = 0; j < C0; j++) acc += sf[pi][j]*lw[j];
        g_h0[(size_t)(p0+pi)*C1 + c] = acc;
        lsum += acc; lsq += acc*acc;
    }
    red[threadIdx.y][c] = make_float2(lsum, lsq);
    __syncthreads();
    if (threadIdx.y == 0) {
        float s = 0.f, q = 0.f;
        #pragma unroll
        for (int r = 0; r < 4; r++) { s += red[r][c].x; q += red[r][c].y; }
        g_pA[blockIdx.x*C1 + c] = s;
        g_pB[blockIdx.x*C1 + c] = q;
    }
}

// ---------------- fold BN stats ----------------
__global__ void fold_kernel(int nblk, int C, float cnt,
                            const float* __restrict__ g, const float* __restrict__ be,
                            int slot)
{
    int c = threadIdx.x;
    if (c >= C) return;
    double s = 0.0, q = 0.0;
    for (int r = 0; r < nblk; r++) { s += (double)g_pA[r*C + c]; q += (double)g_pB[r*C + c]; }
    double m = s / (double)cnt;
    double v = q / (double)cnt - m*m;
    float sc = g[c] * rsqrtf((float)v + EPSV);
    g_scale[slot*256 + c] = sc;
    g_shift[slot*256 + c] = be[c] - (float)m * sc;
}

// ---------------- weight prep ----------------
__global__ void prepw_kernel(const float* __restrict__ W, int N, int Cin,
                             __nv_bfloat16* __restrict__ dst)
{
    int i = blockIdx.x*256 + threadIdx.x;
    if (i >= N*Cin) return;
    int n = i / Cin, c = i % Cin;
    int chunk = c >> 6, k = c & 63;
    float w = W[i];
    __nv_bfloat16 h = __float2bfloat16_rn(w);
    float lo = w - __bfloat162float(h);
    int off = SWZ(n*128 + k*2) >> 1;
    size_t base = (size_t)chunk * (2*N*64);
    dst[base + off] = h;
    dst[base + N*64 + off] = __float2bfloat16_rn(lo);
}

__global__ void prepwt_kernel(const float* __restrict__ wt)
{
    int i = blockIdx.x*256 + threadIdx.x;
    if (i >= C3*C3*3) return;
    int dt = i % 3;
    int c  = (i / 3) % C3;
    int o  = i / (3*C3);
    int chunk = dt*4 + (c >> 6);
    int k = c & 63;
    float w = wt[i];
    __nv_bfloat16 h = __float2bfloat16_rn(w);
    float lo = w - __bfloat162float(h);
    int off = SWZ(o*128 + k*2) >> 1;
    size_t base = (size_t)chunk * (2*C3*64);
    g_wtx[base + off] = h;
    g_wtx[base + C3*64 + off] = __float2bfloat16_rn(lo);
}

// ---------------- pipelined HMMA GEMM (split-bf16 x3) ----------------
#define OFF_W0   32768
#define OFF_W1   65536
#define OFF_BIAS 98304
#define OFF_SS   98816
#define OFF_SC   99840
#define OFF_PS   100864
#define OFF_PQ   101888
#define SMB_GEMM 102912

template<int CIN, int COUT, int NCHUNK, int MODE>
__global__ __launch_bounds__(256, 2) void mma_gemm(
    const float* __restrict__ A, const __nv_bfloat16* __restrict__ Wx,
    const float* __restrict__ bias, int affSlot,
    float* __restrict__ out, float* __restrict__ pA, float* __restrict__ pB)
{
    extern __shared__ __align__(1024) char smem[];
    const int tid = threadIdx.x;
    const int wid = tid >> 5, lane = tid & 31;
    const int warpRow = wid & 1, warpCol = wid >> 1;
    const int rowBase = blockIdx.x * 128;
    const int colBase = blockIdx.y * 128;
    const uint32_t sb32 = smem_u32(smem);

    float* sbias = (float*)(smem + OFF_BIAS);
    float* sS = (float*)(smem + OFF_SS);
    float* sC = (float*)(smem + OFF_SC);
    if (tid < 128) sbias[tid] = bias[colBase + tid];
    for (int e = tid; e < CIN; e += 256) {
        sS[e] = g_scale[affSlot*256 + e];
        sC[e] = g_shift[affSlot*256 + e];
    }
    __syncthreads();   // *** REQUIRED: sS/sC/sbias must be visible before cvt_store ***

    int bb = 0, to = 0, n0 = 0;
    if (MODE == 2) { bb = rowBase/(TOUT*NP); to = (rowBase/NP) % TOUT; n0 = rowBase % NP; }

    auto a_ptr = [&](int chunk, int& cs, int& chBase) -> const float* {
        if (MODE == 2) {
            int dt = chunk >> 2, kc = chunk & 3;
            cs = C3; chBase = kc*64;
            return A + ((size_t)((bb*T_ + to + dt)*NP + n0))*C3 + kc*64;
        } else {
            cs = CIN; chBase = chunk*64;
            return A + (size_t)rowBase*CIN + chunk*64;
        }
    };
    auto cvt_store = [&](float4 v, int f, int chBase) {
        int row = f >> 4;
        int k = (f & 15) * 4;
        int ch = chBase + k;
        v.x = fmaxf(fmaf(v.x, sS[ch+0], sC[ch+0]), 0.f);
        v.y = fmaxf(fmaf(v.y, sS[ch+1], sC[ch+1]), 0.f);
        v.z = fmaxf(fmaf(v.z, sS[ch+2], sC[ch+2]), 0.f);
        v.w = fmaxf(fmaf(v.w, sS[ch+3], sC[ch+3]), 0.f);
        float h0 = __bfloat162float(__float2bfloat16_rn(v.x));
        float h1 = __bfloat162float(__float2bfloat16_rn(v.y));
        float h2 = __bfloat162float(__float2bfloat16_rn(v.z));
        float h3 = __bfloat162float(__float2bfloat16_rn(v.w));
        uint32_t off = SWZ((uint32_t)(row*128 + k*2));
        *(uint2*)(smem + off)         = make_uint2(pkbf(v.x, v.y), pkbf(v.z, v.w));
        *(uint2*)(smem + 16384 + off) = make_uint2(pkbf(v.x - h0, v.y - h1), pkbf(v.z - h2, v.w - h3));
    };
    auto w_cpasync = [&](int chunk, uint32_t wbase) {
        const char* Whi = (const char*)(Wx + (size_t)chunk*2*((size_t)COUT*64) + (size_t)colBase*64);
        const char* Wlo = (const char*)(Wx + (size_t)chunk*2*((size_t)COUT*64) + (size_t)COUT*64 + (size_t)colBase*64);
        #pragma unroll
        for (int i = 0; i < 4; i++) {
            int o = (tid + i*256) * 16;
            cpasync16(sb32 + wbase + o,         Whi + o);
            cpasync16(sb32 + wbase + 16384 + o, Wlo + o);
        }
    };

    float acc[4][4][4] = {};
    float4 Av[4];

    // prologue: prefetch half of A(0) + W(0)
    {
        int cs, chBase;
        const float* Ab = a_ptr(0, cs, chBase);
        #pragma unroll
        for (int i = 0; i < 4; i++) {
            int f = tid + i*256;
            Av[i] = *(const float4*)(Ab + (size_t)(f >> 4)*cs + (f & 15)*4);
        }
        w_cpasync(0, OFF_W0);
        CP_COMMIT();
    }

    for (int chunk = 0; chunk < NCHUNK; chunk++) {
        int cs, chBase;
        const float* Ab = a_ptr(chunk, cs, chBase);
        #pragma unroll
        for (int i = 0; i < 4; i++) cvt_store(Av[i], tid + i*256, chBase);
        #pragma unroll
        for (int i = 4; i < 8; i++) {
            int f = tid + i*256;
            float4 v = *(const float4*)(Ab + (size_t)(f >> 4)*cs + (f & 15)*4);
            cvt_store(v, f, chBase);
        }
        if (chunk + 1 < NCHUNK) {
            int cs2, cb2;
            const float* Ab2 = a_ptr(chunk + 1, cs2, cb2);
            #pragma unroll
            for (int i = 0; i < 4; i++) {
                int f = tid + i*256;
                Av[i] = *(const float4*)(Ab2 + (size_t)(f >> 4)*cs2 + (f & 15)*4);
            }
            w_cpasync(chunk + 1, (chunk + 1) & 1 ? OFF_W1 : OFF_W0);
            CP_COMMIT();
            CP_WAIT(1);
        } else {
            CP_WAIT(0);
        }
        __syncthreads();
        uint32_t wbase = (chunk & 1) ? OFF_W1 : OFF_W0;
        #pragma unroll
        for (int ks = 0; ks < 4; ks++) {
            uint32_t bh[4][2], bl[4][2];
            #pragma unroll
            for (int nt2 = 0; nt2 < 2; nt2++) {
                uint32_t roff = (uint32_t)((warpCol*32 + nt2*16 + ((lane>>4)<<3) + (lane&7))*128
                                           + ks*32 + (((lane>>3)&1)<<4));
                uint32_t ah = sb32 + wbase + SWZ(roff);
                uint32_t al = sb32 + wbase + 16384 + SWZ(roff);
                ldm_x4(ah, bh[nt2*2][0], bh[nt2*2][1], bh[nt2*2+1][0], bh[nt2*2+1][1]);
                ldm_x4(al, bl[nt2*2][0], bl[nt2*2][1], bl[nt2*2+1][0], bl[nt2*2+1][1]);
            }
            #pragma unroll
            for (int mt = 0; mt < 4; mt++) {
                uint32_t roff = (uint32_t)((warpRow*64 + mt*16 + (lane&15))*128
                                           + ks*32 + ((lane>>4)<<4));
                uint32_t ahreg[4], alreg[4];
                ldm_x4(sb32 + SWZ(roff), ahreg[0], ahreg[1], ahreg[2], ahreg[3]);
                ldm_x4(sb32 + 16384 + SWZ(roff), alreg[0], alreg[1], alreg[2], alreg[3]);
                #pragma unroll
                for (int nt = 0; nt < 4; nt++) mma16816(acc[mt][nt], ahreg, bh[nt]);
                #pragma unroll
                for (int nt = 0; nt < 4; nt++) mma16816(acc[mt][nt], ahreg, bl[nt]);
                #pragma unroll
                for (int nt = 0; nt < 4; nt++) mma16816(acc[mt][nt], alreg, bh[nt]);
            }
        }
        __syncthreads();
    }

    // -------- epilogue --------
    #pragma unroll
    for (int nt = 0; nt < 4; nt++) {
        int cl = warpCol*32 + nt*8 + (lane&3)*2;
        float b0 = sbias[cl], b1 = sbias[cl+1];
        #pragma unroll
        for (int mt = 0; mt < 4; mt++) {
            acc[mt][nt][0] += b0; acc[mt][nt][1] += b1;
            acc[mt][nt][2] += b0; acc[mt][nt][3] += b1;
        }
    }
    float* ps = (float*)(smem + OFF_PS);
    float* pq = (float*)(smem + OFF_PQ);
    #pragma unroll
    for (int nt = 0; nt < 4; nt++) {
        float s0 = 0.f, s1 = 0.f, q0 = 0.f, q1 = 0.f;
        #pragma unroll
        for (int mt = 0; mt < 4; mt++) {
            float c0 = acc[mt][nt][0], c1 = acc[mt][nt][1];
            float c2 = acc[mt][nt][2], c3 = acc[mt][nt][3];
            s0 += c0 + c2; s1 += c1 + c3;
            q0 += c0*c0 + c2*c2; q1 += c1*c1 + c3*c3;
        }
        s0 = shfl_sum3(s0); s1 = shfl_sum3(s1);
        q0 = shfl_sum3(q0); q1 = shfl_sum3(q1);
        if (lane < 4) {
            int cl = warpCol*32 + nt*8 + lane*2;
            ps[warpRow*128 + cl] = s0; ps[warpRow*128 + cl + 1] = s1;
            pq[warpRow*128 + cl] = q0; pq[warpRow*128 + cl + 1] = q1;
        }
    }
    if (MODE == 1) {
        #pragma unroll
        for (int mt = 0; mt < 4; mt++) {
            int grow = (rowBase >> 4) + warpRow*4 + mt;
            #pragma unroll
            for (int nt = 0; nt < 4; nt++) {
                float m0 = shfl_max3(fmaxf(acc[mt][nt][0], acc[mt][nt][2]));
                float m1 = shfl_max3(fmaxf(acc[mt][nt][1], acc[mt][nt][3]));
                if (lane < 4) {
                    int cl = colBase + warpCol*32 + nt*8 + lane*2;
                    *(float2*)&out[(size_t)grow*COUT + cl] = make_float2(m0, m1);
                }
            }
        }
    } else {
        float* tile = (float*)smem;
        __syncthreads();
        #pragma unroll
        for (int mt = 0; mt < 4; mt++) {
            int r0 = warpRow*64 + mt*16 + (lane >> 2);
            #pragma unroll
            for (int nt = 0; nt < 4; nt++) {
                int cl = warpCol*32 + nt*8 + (lane&3)*2;
                *(float2*)&tile[(r0)*132 + cl]   = make_float2(acc[mt][nt][0], acc[mt][nt][1]);
                *(float2*)&tile[(r0+8)*132 + cl] = make_float2(acc[mt][nt][2], acc[mt][nt][3]);
            }
        }
        __syncthreads();
        int r = tid >> 1, half = (tid & 1)*64;
        const float* src = tile + r*132 + half;
        float* dst = out + (size_t)(rowBase + r)*COUT + colBase + half;
        #pragma unroll
        for (int i = 0; i < 16; i++)
            *(float4*)(dst + i*4) = *(const float4*)(src + i*4);
    }
    __syncthreads();
    if (tid < 128) {
        pA[(size_t)blockIdx.x*COUT + colBase + tid] = ps[tid] + ps[128 + tid];
        pB[(size_t)blockIdx.x*COUT + colBase + tid] = pq[tid] + pq[128 + tid];
    }
}

// ---------------- final BN + relu -> output ----------------
__global__ void final_kernel(float* __restrict__ out)
{
    int i = blockIdx.x*blockDim.x + threadIdx.x;
    if (i < PT*C3) {
        int c = i & 255;
        out[i] = fmaxf(g_y[i]*g_scale[3*256 + c] + g_shift[3*256 + c], 0.f);
    }
}

// ---------------- launch ----------------
extern "C" void kernel_launch(void* const* d_in, const int* in_sizes, int n_in,
                              void* d_out, int out_size)
{
    (void)in_sizes; (void)n_in; (void)out_size;
    const float* pts = (const float*)d_in[0];
    const float* w0  = (const float*)d_in[1];
    const float* b0  = (const float*)d_in[2];
    const float* gg0 = (const float*)d_in[3];
    const float* be0 = (const float*)d_in[4];
    const float* w1  = (const float*)d_in[5];
    const float* b1  = (const float*)d_in[6];
    const float* gg1 = (const float*)d_in[7];
    const float* be1 = (const float*)d_in[8];
    const float* w2  = (const float*)d_in[9];
    const float* b2  = (const float*)d_in[10];
    const float* gg2 = (const float*)d_in[11];
    const float* be2 = (const float*)d_in[12];
    const float* wt  = (const float*)d_in[13];
    const float* bt  = (const float*)d_in[14];
    const float* ggt = (const float*)d_in[15];
    const float* bet = (const float*)d_in[16];
    float* out = (float*)d_out;

    float *dh0 = nullptr, *dh1 = nullptr, *dxm = nullptr, *dy = nullptr;
    float *dpA = nullptr, *dpB = nullptr;
    __nv_bfloat16 *dw1x = nullptr, *dw2x = nullptr, *dwtx = nullptr;
    cudaGetSymbolAddress((void**)&dh0, g_h0);
    cudaGetSymbolAddress((void**)&dh1, g_h1);
    cudaGetSymbolAddress((void**)&dxm, g_xm);
    cudaGetSymbolAddress((void**)&dy, g_y);
    cudaGetSymbolAddress((void**)&dpA, g_pA);
    cudaGetSymbolAddress((void**)&dpB, g_pB);
    cudaGetSymbolAddress((void**)&dw1x, g_w1x);
    cudaGetSymbolAddress((void**)&dw2x, g_w2x);
    cudaGetSymbolAddress((void**)&dwtx, g_wtx);

    static bool attr_set = false;
    if (!attr_set) {
        cudaFuncSetAttribute(mma_gemm<64,128,1,0>,   cudaFuncAttributeMaxDynamicSharedMemorySize, SMB_GEMM);
        cudaFuncSetAttribute(mma_gemm<128,256,2,1>,  cudaFuncAttributeMaxDynamicSharedMemorySize, SMB_GEMM);
        cudaFuncSetAttribute(mma_gemm<256,256,12,2>, cudaFuncAttributeMaxDynamicSharedMemorySize, SMB_GEMM);
        attr_set = true;
    }

    prepw_kernel<<<(C2*C1 + 255)/256, 256>>>(w1, C2, C1, dw1x);
    prepw_kernel<<<(C3*C2 + 255)/256, 256>>>(w2, C3, C2, dw2x);
    prepwt_kernel<<<(C3*C3*3 + 255)/256, 256>>>(wt);
    knn_kernel<<<B_*NP/4, 128>>>(pts);

    mlp0_kernel<<<P1/64, dim3(64,4)>>>(w0, b0);
    fold_kernel<<<1, C1>>>(P1/64, C1, (float)P1, gg0, be0, 0);

    mma_gemm<64,128,1,0><<<dim3(P1/128, 1), 256, SMB_GEMM>>>(dh0, dw1x, b1, 0, dh1, dpA, dpB);
    fold_kernel<<<1, C2>>>(P1/128, C2, (float)P1, gg1, be1, 1);

    mma_gemm<128,256,2,1><<<dim3(P1/128, 2), 256, SMB_GEMM>>>(dh1, dw2x, b2, 1, dxm, dpA, dpB);
    fold_kernel<<<1, C3>>>(P1/128, C3, (float)P1, gg2, be2, 2);

    mma_gemm<256,256,12,2><<<dim3(PT/128, 2), 256, SMB_GEMM>>>(dxm, dwtx, bt, 2, dy, dpA, dpB);
    fold_kernel<<<1, C3>>>(PT/128, C3, (float)PT, ggt, bet, 3);

    final_kernel<<<(PT*C3 + 255)/256, 256>>>(out);
}